// round 6
// baseline (speedup 1.0000x reference)
#include <cuda_runtime.h>
#include <math.h>
#include <stdint.h>

// ---------------- problem constants ----------------
#define T_TOK 16384
#define DIM   2048
#define EXP   64
#define NTOT  128        // gate(64) + noise(64) outputs
#define NBLK  128        // CTAs, 128 tokens each
#define KT    32         // k per tile
#define NKT   64         // 2048/32
#define PITCH 36         // smem row pitch in floats (32 + 4 pad), 144B
#define A_FL  (128*PITCH)            // floats per A tile
#define STAGE_FL (3*A_FL)            // A + B0 + B1
#define NSTAGE 3
#define DYN_BYTES (NSTAGE*STAGE_FL*4)   // 165888
#define LPITCH 132                   // epilogue logits pitch
#define TIE_EPS 1e-3f                // exact-recompute band around top2/top3 boundary

// ---------------- device scratch ----------------
__device__ __align__(16) float g_Bs[2 * NTOT * DIM];   // tf32-valued W split, [term][n][k]
__device__ float g_psum[NBLK * EXP];
__device__ float g_cnt [NBLK * EXP];

// ---------------- helpers ----------------
__device__ __forceinline__ float to_tf32(float f) {
    float r;
    asm("cvt.rna.tf32.f32 %0, %1;" : "=f"(r) : "f"(f));
    return r;
}
__device__ __forceinline__ uint32_t s2u(const void* p) {
    uint32_t a;
    asm("{ .reg .u64 t; cvta.to.shared.u64 t, %1; cvt.u32.u64 %0, t; }" : "=r"(a) : "l"(p));
    return a;
}
__device__ __forceinline__ void cp16(uint32_t s, const void* g) {
    asm volatile("cp.async.cg.shared.global [%0], [%1], 16;" :: "r"(s), "l"(g));
}
__device__ __forceinline__ void cp_commit() { asm volatile("cp.async.commit_group;"); }
__device__ __forceinline__ void cp_wait2()  { asm volatile("cp.async.wait_group 2;"); }

__device__ __forceinline__ void mma8(float* c, float a0, float a1, float a2, float a3,
                                     float b0, float b1) {
    asm volatile(
        "mma.sync.aligned.m16n8k8.row.col.f32.tf32.tf32.f32 "
        "{%0,%1,%2,%3}, {%4,%5,%6,%7}, {%8,%9}, {%0,%1,%2,%3};"
        : "+f"(c[0]), "+f"(c[1]), "+f"(c[2]), "+f"(c[3])
        : "r"(__float_as_uint(a0)), "r"(__float_as_uint(a1)),
          "r"(__float_as_uint(a2)), "r"(__float_as_uint(a3)),
          "r"(__float_as_uint(b0)), "r"(__float_as_uint(b1)));
}
__device__ __forceinline__ float softplus_eps(float nv) {
    return fmaxf(nv, 0.f) + log1pf(expf(-fabsf(nv))) + 0.01f;
}

// ---------------- kernel 0: pre-split W into 2 tf32 terms ----------------
__global__ void splitW_kernel(const float* __restrict__ Wg, const float* __restrict__ Wn) {
    int idx = blockIdx.x * 256 + threadIdx.x;      // 0..262143 over [n][k]
    int n = idx >> 11, k = idx & 2047;
    float w = (n < 64) ? Wg[n * 2048 + k] : Wn[(n - 64) * 2048 + k];
    float w0 = to_tf32(w);
    float w1 = to_tf32(w - w0);
    g_Bs[idx] = w0;                                 // term 0
    g_Bs[NTOT * DIM + idx] = w1;                    // term 1
}

// ---------------- kernel 1: fused split-tf32 mma.sync GEMM + epilogue ----------------
__global__ __launch_bounds__(256, 1)
void moe_kernel(const float* __restrict__ x, const float* __restrict__ rn,
                const float* __restrict__ bg, const float* __restrict__ Wg,
                const float* __restrict__ Wn, float* __restrict__ out)
{
    extern __shared__ float dyn[];
    __shared__ float s_bg[EXP];
    __shared__ float m_s[128], is_s[128], p1_s[128];
    __shared__ int   hi_s[128], li_s[128];
    __shared__ int   s_flags[128];
    __shared__ int   s_nflag;
    __shared__ float s_resc[128];

    const int tid  = threadIdx.x;
    const int lane = tid & 31;
    const int wid  = tid >> 5;
    const int wm   = wid & 1;        // 0,1 -> 64 rows each
    const int wn   = wid >> 1;       // 0..3 -> 32 cols each
    const uint32_t sb = s2u(dyn);

    if (tid < EXP) s_bg[tid] = bg[tid];
    if (tid == 0) s_nflag = 0;

    const int t0 = blockIdx.x * 128;
    const float* xb = x + (size_t)t0 * DIM;

    // staging thread assignments (byte offsets inside a stage)
    int aM[4], aOff[4];
#pragma unroll
    for (int i = 0; i < 4; ++i) {
        int idx = tid + 256 * i;            // 0..1023 float4 slots
        aM[i]   = idx >> 3;
        aOff[i] = (idx >> 3) * (PITCH * 4) + (idx & 7) * 16;
    }
    int bT[8], bN[8], bOff[8];
#pragma unroll
    for (int i = 0; i < 8; ++i) {
        int idx = tid + 256 * i;            // 0..2047
        int term = idx >> 10, rem = idx & 1023;
        bT[i] = term; bN[i] = rem >> 3;
        bOff[i] = (1 + term) * (A_FL * 4) + (rem >> 3) * (PITCH * 4) + (rem & 7) * 16;
    }

#define STAGE(kb_) do {                                                        \
    int kreal = (kb_) * KT;                                                    \
    uint32_t s0 = sb + ((kb_) % NSTAGE) * (STAGE_FL * 4);                      \
    _Pragma("unroll")                                                          \
    for (int i = 0; i < 4; ++i)                                                \
        cp16(s0 + aOff[i], xb + (size_t)aM[i] * DIM + kreal + ((tid + 256*i) & 7) * 4); \
    _Pragma("unroll")                                                          \
    for (int i = 0; i < 8; ++i)                                                \
        cp16(s0 + bOff[i], g_Bs + ((size_t)(bT[i] * NTOT + bN[i])) * DIM + kreal + ((tid + 256*i) & 7) * 4); \
    cp_commit();                                                               \
} while (0)

    STAGE(0); STAGE(1); STAGE(2);

    float c[4][4][4];
#pragma unroll
    for (int a = 0; a < 4; ++a)
#pragma unroll
        for (int b = 0; b < 4; ++b)
#pragma unroll
            for (int d = 0; d < 4; ++d) c[a][b][d] = 0.f;

    const int mbase = wm * 64 + (lane >> 2);
    const int nbase = wn * 32 + (lane >> 2);
    const int kc    = lane & 3;

    for (int kb = 0; kb < NKT; ++kb) {
        cp_wait2();
        __syncthreads();
        const float* sA  = dyn + (kb % NSTAGE) * STAGE_FL;
        const float* sB0 = sA + A_FL;
        const float* sB1 = sB0 + A_FL;
#pragma unroll
        for (int ks = 0; ks < 4; ++ks) {
            const int k0 = ks * 8 + kc;
            float b0r[4][2], b1r[4][2];
#pragma unroll
            for (int nt = 0; nt < 4; ++nt) {
                int nrow = (nbase + nt * 8) * PITCH;
                b0r[nt][0] = sB0[nrow + k0];
                b0r[nt][1] = sB0[nrow + k0 + 4];
                b1r[nt][0] = sB1[nrow + k0];
                b1r[nt][1] = sB1[nrow + k0 + 4];
            }
#pragma unroll
            for (int mt = 0; mt < 4; ++mt) {
                int r0 = (mbase + mt * 16) * PITCH;
                int r1 = r0 + 8 * PITCH;
                float x0 = sA[r0 + k0], x1 = sA[r1 + k0];
                float x2 = sA[r0 + k0 + 4], x3 = sA[r1 + k0 + 4];
                float a00 = to_tf32(x0), a01 = to_tf32(x1);
                float a02 = to_tf32(x2), a03 = to_tf32(x3);
                float a10 = to_tf32(x0 - a00), a11 = to_tf32(x1 - a01);
                float a12 = to_tf32(x2 - a02), a13 = to_tf32(x3 - a03);
#pragma unroll
                for (int nt = 0; nt < 4; ++nt) {
                    mma8(c[mt][nt], a00, a01, a02, a03, b0r[nt][0], b0r[nt][1]); // x0*w0
                    mma8(c[mt][nt], a00, a01, a02, a03, b1r[nt][0], b1r[nt][1]); // x0*w1
                    mma8(c[mt][nt], a10, a11, a12, a13, b0r[nt][0], b0r[nt][1]); // x1*w0
                }
            }
        }
        __syncthreads();
        if (kb + NSTAGE < NKT) STAGE(kb + NSTAGE);
        else cp_commit();     // keep pending==3 invariant (tail)
    }
#undef STAGE

    // -------- write C to smem logits buffer [128][LPITCH] --------
    float* sL = dyn;
#pragma unroll
    for (int mt = 0; mt < 4; ++mt) {
#pragma unroll
        for (int nt = 0; nt < 4; ++nt) {
            int row = wm * 64 + mt * 16 + (lane >> 2);
            int col = wn * 32 + nt * 8 + 2 * (lane & 3);
            *(float2*)&sL[row * LPITCH + col] = make_float2(c[mt][nt][0], c[mt][nt][1]);
            *(float2*)&sL[(row + 8) * LPITCH + col] = make_float2(c[mt][nt][2], c[mt][nt][3]);
        }
    }
    __syncthreads();

    // -------- phase 1: per-token epilogue (thread = token) --------
    if (tid < 128) {
        const int t = tid;
        const int tok = t0 + t;
        float* row = sL + t * LPITCH;
        float hv = -3.4e38f, lv = -3.4e38f, tv = -3.4e38f;
        int hi = 0, li = 0;
#pragma unroll 8
        for (int e = 0; e < 64; ++e) {
            float g  = row[e];
            float nv = row[64 + e];
            float v  = g + s_bg[e] + rn[(size_t)tok * EXP + e] * softplus_eps(nv);
            row[e] = v;                       // overwrite gate half with noisy logit
            if (v > hv)      { tv = lv; lv = hv; li = hi; hv = v; hi = e; }
            else if (v > lv) { tv = lv; lv = v; li = e; }
            else if (v > tv) { tv = v; }
        }
        float ssum = 0.f;
#pragma unroll 8
        for (int e = 0; e < 64; ++e) ssum += expf(row[e] - hv);
        m_s[t] = hv; is_s[t] = 1.f / ssum; hi_s[t] = hi; li_s[t] = li;
        float ebt = expf(lv - hv);
        float den = 1.f / (1.f + ebt);
        float p0 = den, p1 = ebt * den;
        p1_s[t] = p1;
        float4 z = make_float4(0.f, 0.f, 0.f, 0.f);
        float4* orow = (float4*)(out + (size_t)tok * EXP);
#pragma unroll
        for (int q = 0; q < 16; ++q) orow[q] = z;
        out[(size_t)tok * EXP + hi] = p0;
        out[(size_t)tok * EXP + li] = p1;
        // which-expert-is-second boundary inside tf32 error band -> exact recompute
        if (lv - tv < TIE_EPS) {
            int slot = atomicAdd(&s_nflag, 1);
            s_flags[slot] = t;
        }
    }
    __syncthreads();

    // -------- phase 2: exact fp32 rescue for near-tie tokens --------
    const int nflag = s_nflag;
    for (int f = 0; f < nflag; ++f) {
        const int t = s_flags[f];
        const int tok = t0 + t;
        if (tid < 128) {
            const int e = tid & 63;
            const float* wr = (tid < 64) ? (Wg + (size_t)e * DIM) : (Wn + (size_t)e * DIM);
            const float* xr = x + (size_t)tok * DIM;
            float a0 = 0.f, a1 = 0.f, a2 = 0.f, a3 = 0.f;
            for (int k = 0; k < DIM; k += 4) {
                float4 xv = *(const float4*)(xr + k);
                float4 wv = *(const float4*)(wr + k);
                a0 = fmaf(xv.x, wv.x, a0); a1 = fmaf(xv.y, wv.y, a1);
                a2 = fmaf(xv.z, wv.z, a2); a3 = fmaf(xv.w, wv.w, a3);
            }
            s_resc[tid] = (a0 + a1) + (a2 + a3);
        }
        __syncthreads();
        if (tid < 64) {
            float g  = s_resc[tid] + s_bg[tid];
            float nv = s_resc[64 + tid];
            sL[t * LPITCH + tid] = g + rn[(size_t)tok * EXP + tid] * softplus_eps(nv);
        }
        __syncthreads();
        if (tid == 0) {
            float* row = sL + t * LPITCH;
            float hv = -3.4e38f, lv = -3.4e38f;
            int hi = 0, li = 0;
            for (int e = 0; e < 64; ++e) {
                float v = row[e];
                if (v > hv)      { lv = hv; li = hi; hv = v; hi = e; }
                else if (v > lv) { lv = v; li = e; }
            }
            float ssum = 0.f;
            for (int e = 0; e < 64; ++e) ssum += expf(row[e] - hv);
            m_s[t] = hv; is_s[t] = 1.f / ssum; hi_s[t] = hi; li_s[t] = li;
            float ebt = expf(lv - hv);
            float den = 1.f / (1.f + ebt);
            float p0 = den, p1 = ebt * den;
            p1_s[t] = p1;
            float* orow = out + (size_t)tok * EXP;
            for (int e = 0; e < 64; ++e) orow[e] = 0.f;
            orow[hi] = p0;
            orow[li] = p1;
        }
        __syncthreads();
    }

    // -------- phase 3: deterministic per-expert partials for aux loss --------
    if (tid < EXP) {
        float ps = 0.f, ct = 0.f;
        for (int t2 = 0; t2 < 128; ++t2) {
            ps += expf(sL[t2 * LPITCH + tid] - m_s[t2]) * is_s[t2];
            ct += (hi_s[t2] == tid ? 1.f : 0.f)
                + ((li_s[t2] == tid && p1_s[t2] > 0.f) ? 1.f : 0.f);
        }
        g_psum[blockIdx.x * EXP + tid] = ps;
        g_cnt [blockIdx.x * EXP + tid] = ct;
    }
}

// ---------------- kernel 2: aux loss (deterministic) ----------------
__global__ void aux_kernel(float* __restrict__ out, int idx) {
    const int e = threadIdx.x;   // 64 threads
    float ps = 0.f, ct = 0.f;
    for (int b = 0; b < NBLK; ++b) {
        ps += g_psum[b * EXP + e];
        ct += g_cnt [b * EXP + e];
    }
    float term = (ct * (1.f / (float)T_TOK)) * (ps * (1.f / (float)T_TOK));
#pragma unroll
    for (int off = 16; off > 0; off >>= 1)
        term += __shfl_xor_sync(0xffffffffu, term, off);
    __shared__ float sm[2];
    if ((e & 31) == 0) sm[e >> 5] = term;
    __syncthreads();
    if (e == 0) out[idx] = (sm[0] + sm[1]) * (float)EXP;
}

extern "C" void kernel_launch(void* const* d_in, const int* in_sizes, int n_in,
                              void* d_out, int out_size) {
    (void)in_sizes; (void)n_in;
    const float* x  = (const float*)d_in[0];   // [16384, 2048]
    const float* rn = (const float*)d_in[1];   // [16384, 64]
    const float* Wg = (const float*)d_in[2];   // [64, 2048]
    const float* bg = (const float*)d_in[3];   // [64]
    const float* Wn = (const float*)d_in[4];   // [64, 2048]
    float* out = (float*)d_out;

    cudaFuncSetAttribute(moe_kernel, cudaFuncAttributeMaxDynamicSharedMemorySize, DYN_BYTES);
    splitW_kernel<<<1024, 256>>>(Wg, Wn);
    moe_kernel<<<NBLK, 256, DYN_BYTES>>>(x, rn, bg, Wg, Wn, out);
    aux_kernel<<<1, EXP>>>(out, out_size - 1);
}

// round 10
// speedup vs baseline: 1.2598x; 1.2598x over previous
#include <cuda_runtime.h>
#include <cuda_fp16.h>
#include <math.h>
#include <stdint.h>

// ---------------- problem constants ----------------
#define T_TOK 16384
#define DIM   2048
#define EXP   64
#define NTOT  128        // gate(64) + noise(64) outputs
#define NBLK  128        // CTAs, 128 tokens each
#define THREADS 512
#define KT    32         // k per tile
#define NKT   64         // 2048/32
#define LPITCH 132       // epilogue logits pitch (floats)
#define TIE_EPS 1e-3f

// smem byte layout: A bufs [2][2 terms][128 rows][40 halves], then B same
#define ROWB   80u                    // 40 halves * 2B, conflict-free pitch
#define A_TSTR 10240u                 // one term: 128*80
#define BUF_SZ 20480u                 // 2 terms
#define B_BASE 40960u                 // B region after 2 A buffers
#define DYN_BYTES 81920               // 2*(2*20480)

// ---------------- device scratch ----------------
__device__ __align__(16) __half g_Bh[2][NTOT * DIM];   // W split into 2 fp16 terms, [term][n][k]
__device__ float g_psum[NBLK * EXP];
__device__ float g_cnt [NBLK * EXP];

// ---------------- helpers ----------------
__device__ __forceinline__ uint32_t pack2(__half a, __half b) {
    return (uint32_t)__half_as_ushort(a) | ((uint32_t)__half_as_ushort(b) << 16);
}
__device__ __forceinline__ void mma16(float* c, const uint32_t* a, const uint32_t* b) {
    asm volatile(
        "mma.sync.aligned.m16n8k16.row.col.f32.f16.f16.f32 "
        "{%0,%1,%2,%3}, {%4,%5,%6,%7}, {%8,%9}, {%0,%1,%2,%3};"
        : "+f"(c[0]), "+f"(c[1]), "+f"(c[2]), "+f"(c[3])
        : "r"(a[0]), "r"(a[1]), "r"(a[2]), "r"(a[3]), "r"(b[0]), "r"(b[1]));
}
__device__ __forceinline__ float softplus_eps(float nv) {
    return fmaxf(nv, 0.f) + log1pf(expf(-fabsf(nv))) + 0.01f;
}

// ---------------- kernel 0: pre-split W into 2 fp16 terms ----------------
__global__ void splitW_kernel(const float* __restrict__ Wg, const float* __restrict__ Wn) {
    int idx = blockIdx.x * 256 + threadIdx.x;      // 0..262143 over [n][k]
    int n = idx >> 11, k = idx & 2047;
    float w = (n < 64) ? Wg[n * 2048 + k] : Wn[(n - 64) * 2048 + k];
    __half h0 = __float2half_rn(w);
    __half h1 = __float2half_rn(w - __half2float(h0));   // exact residual, re-rounded
    g_Bh[0][idx] = h0;
    g_Bh[1][idx] = h1;
}

// ---------------- kernel 1: fused fp16-split mma GEMM + epilogue ----------------
__global__ __launch_bounds__(THREADS, 1)
void moe_kernel(const float* __restrict__ x, const float* __restrict__ rn,
                const float* __restrict__ bg, const float* __restrict__ Wg,
                const float* __restrict__ Wn, float* __restrict__ out)
{
    extern __shared__ char dyn[];
    __shared__ float s_bg[EXP];
    __shared__ float m_s[128], is_s[128], p1_s[128];
    __shared__ int   hi_s[128], li_s[128];
    __shared__ int   s_flags[128];
    __shared__ int   s_nflag;
    __shared__ float s_resc[128];

    const int tid  = threadIdx.x;
    const int lane = tid & 31;
    const int wid  = tid >> 5;       // 0..15
    const int wm   = wid & 3;        // 4 row-groups of 32
    const int wn4  = wid >> 2;       // 4 col-groups of 32
    const int g    = lane >> 2;      // 0..7
    const int cq   = lane & 3;       // 0..3

    if (tid < EXP) s_bg[tid] = bg[tid];
    if (tid == 0) s_nflag = 0;

    const int t0 = blockIdx.x * 128;
    const float* xb = x + (size_t)t0 * DIM;

    // -------- staging assignments --------
    // A: thread j -> row j>>2, k-quarter (j&3)*8 (8 consecutive k)
    const int arow = tid >> 2;
    const int akq  = (tid & 3) * 8;
    // B: thread j -> term j>>8, n (j&255)>>1, k-half ((j&1)*16) (16 consecutive k)
    const int bterm = tid >> 8;
    const int bn    = (tid & 255) >> 1;
    const int bkh   = (tid & 1) * 16;

    float4 xr0, xr1;           // A prefetch regs (8 floats)
    uint4  brA, brB;           // B prefetch regs (16 halves)

#define LDG_TILE(kb_) do {                                                     \
    const float* ap = xb + (size_t)arow * DIM + (kb_) * KT + akq;              \
    xr0 = *(const float4*)ap; xr1 = *(const float4*)(ap + 4);                  \
    const uint4* bp = (const uint4*)&g_Bh[bterm][(size_t)bn * DIM + (kb_) * KT + bkh]; \
    brA = bp[0]; brB = bp[1];                                                  \
} while (0)

#define CVT_ST_TILE(buf_) do {                                                 \
    char* ab = dyn + (buf_) * BUF_SZ;                                          \
    float xv[8] = {xr0.x, xr0.y, xr0.z, xr0.w, xr1.x, xr1.y, xr1.z, xr1.w};    \
    uint32_t w0[4], w1[4];                                                     \
    _Pragma("unroll")                                                          \
    for (int v = 0; v < 4; ++v) {                                              \
        __half h0a = __float2half_rn(xv[2*v]);                                 \
        __half h0b = __float2half_rn(xv[2*v+1]);                               \
        w0[v] = pack2(h0a, h0b);                                               \
        __half h1a = __float2half_rn(xv[2*v]   - __half2float(h0a));           \
        __half h1b = __float2half_rn(xv[2*v+1] - __half2float(h0b));           \
        w1[v] = pack2(h1a, h1b);                                               \
    }                                                                          \
    *(uint4*)(ab + (uint32_t)arow * ROWB + akq * 2)          = make_uint4(w0[0],w0[1],w0[2],w0[3]); \
    *(uint4*)(ab + A_TSTR + (uint32_t)arow * ROWB + akq * 2) = make_uint4(w1[0],w1[1],w1[2],w1[3]); \
    char* bb = dyn + B_BASE + (buf_) * BUF_SZ + bterm * A_TSTR;                \
    *(uint4*)(bb + (uint32_t)bn * ROWB + bkh * 2)      = brA;                  \
    *(uint4*)(bb + (uint32_t)bn * ROWB + bkh * 2 + 16) = brB;                  \
} while (0)

    float c[2][4][4];
#pragma unroll
    for (int a = 0; a < 2; ++a)
#pragma unroll
        for (int b = 0; b < 4; ++b)
#pragma unroll
            for (int d = 0; d < 4; ++d) c[a][b][d] = 0.f;

    LDG_TILE(0);
    CVT_ST_TILE(0);
    __syncthreads();

    for (int kb = 0; kb < NKT; ++kb) {
        const int buf = kb & 1;
        if (kb + 1 < NKT) LDG_TILE(kb + 1);   // latency overlaps mma below

        const char* sa = dyn + buf * BUF_SZ;
        const char* sb = dyn + B_BASE + buf * BUF_SZ;
#pragma unroll
        for (int ks = 0; ks < 2; ++ks) {
            const uint32_t k0b = (uint32_t)(ks * 16 + 2 * cq) * 2;   // byte offset of k-pair
            uint32_t A_[2][2][4], B_[2][4][2];
#pragma unroll
            for (int t = 0; t < 2; ++t)
#pragma unroll
                for (int mt = 0; mt < 2; ++mt) {
                    uint32_t rb = (uint32_t)(wm * 32 + mt * 16 + g) * ROWB + t * A_TSTR;
                    A_[t][mt][0] = *(const uint32_t*)(sa + rb + k0b);
                    A_[t][mt][1] = *(const uint32_t*)(sa + rb + 8 * ROWB + k0b);
                    A_[t][mt][2] = *(const uint32_t*)(sa + rb + k0b + 16);
                    A_[t][mt][3] = *(const uint32_t*)(sa + rb + 8 * ROWB + k0b + 16);
                }
#pragma unroll
            for (int t = 0; t < 2; ++t)
#pragma unroll
                for (int nt = 0; nt < 4; ++nt) {
                    uint32_t nb = (uint32_t)(wn4 * 32 + nt * 8 + g) * ROWB + t * A_TSTR;
                    B_[t][nt][0] = *(const uint32_t*)(sb + nb + k0b);
                    B_[t][nt][1] = *(const uint32_t*)(sb + nb + k0b + 16);
                }
#pragma unroll
            for (int mt = 0; mt < 2; ++mt)
#pragma unroll
                for (int nt = 0; nt < 4; ++nt) {
                    mma16(c[mt][nt], A_[0][mt], B_[0][nt]);   // x0*w0
                    mma16(c[mt][nt], A_[0][mt], B_[1][nt]);   // x0*w1
                    mma16(c[mt][nt], A_[1][mt], B_[0][nt]);   // x1*w0
                }
        }
        __syncthreads();                       // all warps done reading buf
        if (kb + 1 < NKT) {
            CVT_ST_TILE((kb + 1) & 1);
            __syncthreads();                   // next tile visible
        }
    }
#undef LDG_TILE
#undef CVT_ST_TILE

    // -------- write C to smem logits buffer [128][LPITCH] (reuses dyn) --------
    float* sL = (float*)dyn;
#pragma unroll
    for (int mt = 0; mt < 2; ++mt)
#pragma unroll
        for (int nt = 0; nt < 4; ++nt) {
            int row = wm * 32 + mt * 16 + g;
            int col = wn4 * 32 + nt * 8 + 2 * cq;
            *(float2*)&sL[row * LPITCH + col]       = make_float2(c[mt][nt][0], c[mt][nt][1]);
            *(float2*)&sL[(row + 8) * LPITCH + col] = make_float2(c[mt][nt][2], c[mt][nt][3]);
        }
    __syncthreads();

    // -------- phase 1: per-token epilogue (thread = token) --------
    if (tid < 128) {
        const int t = tid;
        const int tok = t0 + t;
        float* row = sL + t * LPITCH;
        float hv = -3.4e38f, lv = -3.4e38f, tv = -3.4e38f;
        int hi = 0, li = 0;
#pragma unroll 8
        for (int e = 0; e < 64; ++e) {
            float gg = row[e];
            float nv = row[64 + e];
            float v  = gg + s_bg[e] + rn[(size_t)tok * EXP + e] * softplus_eps(nv);
            row[e] = v;                       // overwrite gate half with noisy logit
            if (v > hv)      { tv = lv; lv = hv; li = hi; hv = v; hi = e; }
            else if (v > lv) { tv = lv; lv = v; li = e; }
            else if (v > tv) { tv = v; }
        }
        float ssum = 0.f;
#pragma unroll 8
        for (int e = 0; e < 64; ++e) ssum += expf(row[e] - hv);
        m_s[t] = hv; is_s[t] = 1.f / ssum; hi_s[t] = hi; li_s[t] = li;
        float ebt = expf(lv - hv);
        float den = 1.f / (1.f + ebt);
        float p0 = den, p1 = ebt * den;
        p1_s[t] = p1;
        float4 z = make_float4(0.f, 0.f, 0.f, 0.f);
        float4* orow = (float4*)(out + (size_t)tok * EXP);
#pragma unroll
        for (int q = 0; q < 16; ++q) orow[q] = z;
        out[(size_t)tok * EXP + hi] = p0;
        out[(size_t)tok * EXP + li] = p1;
        // expert-2 boundary inside split-fp16 error band -> exact recompute
        if (lv - tv < TIE_EPS) {
            int slot = atomicAdd(&s_nflag, 1);
            s_flags[slot] = t;
        }
    }
    __syncthreads();

    // -------- phase 2: exact fp32 rescue for near-tie tokens --------
    const int nflag = s_nflag;
    for (int f = 0; f < nflag; ++f) {
        const int t = s_flags[f];
        const int tok = t0 + t;
        if (tid < 128) {
            const int e = tid & 63;
            const float* wr = (tid < 64) ? (Wg + (size_t)e * DIM) : (Wn + (size_t)e * DIM);
            const float* xr = x + (size_t)tok * DIM;
            float a0 = 0.f, a1 = 0.f, a2 = 0.f, a3 = 0.f;
            for (int k = 0; k < DIM; k += 4) {
                float4 xv = *(const float4*)(xr + k);
                float4 wv = *(const float4*)(wr + k);
                a0 = fmaf(xv.x, wv.x, a0); a1 = fmaf(xv.y, wv.y, a1);
                a2 = fmaf(xv.z, wv.z, a2); a3 = fmaf(xv.w, wv.w, a3);
            }
            s_resc[tid] = (a0 + a1) + (a2 + a3);
        }
        __syncthreads();
        if (tid < 64) {
            float gg = s_resc[tid] + s_bg[tid];
            float nv = s_resc[64 + tid];
            sL[t * LPITCH + tid] = gg + rn[(size_t)tok * EXP + tid] * softplus_eps(nv);
        }
        __syncthreads();
        if (tid == 0) {
            float* row = sL + t * LPITCH;
            float hv = -3.4e38f, lv = -3.4e38f;
            int hi = 0, li = 0;
            for (int e = 0; e < 64; ++e) {
                float v = row[e];
                if (v > hv)      { lv = hv; li = hi; hv = v; hi = e; }
                else if (v > lv) { lv = v; li = e; }
            }
            float ssum = 0.f;
            for (int e = 0; e < 64; ++e) ssum += expf(row[e] - hv);
            m_s[t] = hv; is_s[t] = 1.f / ssum; hi_s[t] = hi; li_s[t] = li;
            float ebt = expf(lv - hv);
            float den = 1.f / (1.f + ebt);
            float p0 = den, p1 = ebt * den;
            p1_s[t] = p1;
            float* orow = out + (size_t)tok * EXP;
            for (int e = 0; e < 64; ++e) orow[e] = 0.f;
            orow[hi] = p0;
            orow[li] = p1;
        }
        __syncthreads();
    }

    // -------- phase 3: deterministic per-expert partials for aux loss --------
    if (tid < EXP) {
        float ps = 0.f, ct = 0.f;
        for (int t2 = 0; t2 < 128; ++t2) {
            ps += expf(sL[t2 * LPITCH + tid] - m_s[t2]) * is_s[t2];
            ct += (hi_s[t2] == tid ? 1.f : 0.f)
                + ((li_s[t2] == tid && p1_s[t2] > 0.f) ? 1.f : 0.f);
        }
        g_psum[blockIdx.x * EXP + tid] = ps;
        g_cnt [blockIdx.x * EXP + tid] = ct;
    }
}

// ---------------- kernel 2: aux loss (deterministic) ----------------
__global__ void aux_kernel(float* __restrict__ out, int idx) {
    const int e = threadIdx.x;   // 64 threads
    float ps = 0.f, ct = 0.f;
    for (int b = 0; b < NBLK; ++b) {
        ps += g_psum[b * EXP + e];
        ct += g_cnt [b * EXP + e];
    }
    float term = (ct * (1.f / (float)T_TOK)) * (ps * (1.f / (float)T_TOK));
#pragma unroll
    for (int off = 16; off > 0; off >>= 1)
        term += __shfl_xor_sync(0xffffffffu, term, off);
    __shared__ float sm[2];
    if ((e & 31) == 0) sm[e >> 5] = term;
    __syncthreads();
    if (e == 0) out[idx] = (sm[0] + sm[1]) * (float)EXP;
}

extern "C" void kernel_launch(void* const* d_in, const int* in_sizes, int n_in,
                              void* d_out, int out_size) {
    (void)in_sizes; (void)n_in;
    const float* x  = (const float*)d_in[0];   // [16384, 2048]
    const float* rn = (const float*)d_in[1];   // [16384, 64]
    const float* Wg = (const float*)d_in[2];   // [64, 2048]
    const float* bg = (const float*)d_in[3];   // [64]
    const float* Wn = (const float*)d_in[4];   // [64, 2048]
    float* out = (float*)d_out;

    cudaFuncSetAttribute(moe_kernel, cudaFuncAttributeMaxDynamicSharedMemorySize, DYN_BYTES);
    splitW_kernel<<<1024, 256>>>(Wg, Wn);
    moe_kernel<<<NBLK, THREADS, DYN_BYTES>>>(x, rn, bg, Wg, Wn, out);
    aux_kernel<<<1, EXP>>>(out, out_size - 1);
}